// round 4
// baseline (speedup 1.0000x reference)
#include <cuda_runtime.h>
#include <cuda_bf16.h>

// GroupedEmbeddingBag: T tables [N, D] fp32; per table L indices pooled into B
// bags (sum, include_last_offset). Output [B, T*D].
//
// R4: CTA-per-bag (128 thr, 4 warps interleaved over the bag) — unchanged
// structure from R3 (t-major grid order = sequential table processing keeps
// the ~102MB active table resident in 126MB L2; measured traffic is ~97% of
// compulsory, do not perturb). New in R4: fully-batched gathers — the 4 index
// loads per batch are unconditional (address-clamped, always in-bounds) and
// the 4 row gathers are predicated, so EVERY batch, including the bag tail,
// keeps 4 independent 512B row loads in flight (R3's scalar tail ran ~30% of
// gathers at MLP=1).

#define T_TABLES 8
#define N_ROWS   200000
#define D_DIM    128
#define B_BAGS   8192
#define L_IDX    163840

__global__ __launch_bounds__(128, 16)
void grouped_embedding_bag_kernel(const float*  __restrict__ weights,
                                  const int*    __restrict__ values,
                                  const int*    __restrict__ offsets,
                                  float*        __restrict__ out)
{
    const int t = blockIdx.x >> 13;           // / B_BAGS  (t-major: keep!)
    const int b = blockIdx.x & (B_BAGS - 1);
    const int warp = threadIdx.x >> 5;        // 0..3
    const int lane = threadIdx.x & 31;

    const int* __restrict__ offs_t = offsets + t * (B_BAGS + 1) + b;
    const int start = __ldg(offs_t);
    const int end   = __ldg(offs_t + 1);

    const int* __restrict__ vals_t = values + (size_t)t * L_IDX;
    const float4* __restrict__ base =
        reinterpret_cast<const float4*>(weights + (size_t)t * N_ROWS * D_DIM) + lane;

    float4 acc = make_float4(0.f, 0.f, 0.f, 0.f);

    // Warp `warp` owns indices start+warp, start+warp+4, ... (stride 4).
    // Each loop body issues 4 independent index loads (clamped -> always
    // valid) followed by 4 predicated row gathers: MLP=4 even on the tail.
    const int last = end - 1;                 // valid iff end > start
    for (int i = start + warp; i < end; i += 16) {
        const int j1 = i + 4, j2 = i + 8, j3 = i + 12;
        // Clamped, unconditional index loads (all in [start, end) when the
        // loop runs, so always in-bounds of values[]).
        const int i0 = __ldg(vals_t + i);
        const int i1 = __ldg(vals_t + (j1 < end ? j1 : last));
        const int i2 = __ldg(vals_t + (j2 < end ? j2 : last));
        const int i3 = __ldg(vals_t + (j3 < end ? j3 : last));

        const float4 v0 = __ldg(base + (size_t)i0 * 32);
        acc.x += v0.x; acc.y += v0.y; acc.z += v0.z; acc.w += v0.w;
        if (j1 < end) {
            const float4 v = __ldg(base + (size_t)i1 * 32);
            acc.x += v.x; acc.y += v.y; acc.z += v.z; acc.w += v.w;
        }
        if (j2 < end) {
            const float4 v = __ldg(base + (size_t)i2 * 32);
            acc.x += v.x; acc.y += v.y; acc.z += v.z; acc.w += v.w;
        }
        if (j3 < end) {
            const float4 v = __ldg(base + (size_t)i3 * 32);
            acc.x += v.x; acc.y += v.y; acc.z += v.z; acc.w += v.w;
        }
    }

    // Reduce 4 warps' partials through smem.
    __shared__ float4 red[4][32];
    red[warp][lane] = acc;
    __syncthreads();

    if (warp == 0) {
        const float4 a1 = red[1][lane];
        const float4 a2 = red[2][lane];
        const float4 a3 = red[3][lane];
        acc.x += (a1.x + a2.x) + a3.x;
        acc.y += (a1.y + a2.y) + a3.y;
        acc.z += (a1.z + a2.z) + a3.z;
        acc.w += (a1.w + a2.w) + a3.w;
        float4* __restrict__ o =
            reinterpret_cast<float4*>(out + (size_t)b * (T_TABLES * D_DIM) + t * D_DIM) + lane;
        *o = acc;
    }
}

extern "C" void kernel_launch(void* const* d_in, const int* in_sizes, int n_in,
                              void* d_out, int out_size)
{
    const float* weights = (const float*)d_in[0];  // [T, N, D] f32
    const int*   values  = (const int*)  d_in[1];  // [T, L]    i32
    const int*   offsets = (const int*)  d_in[2];  // [T, B+1]  i32
    float*       out     = (float*)d_out;          // [B, T*D]  f32

    const int blocks = T_TABLES * B_BAGS;          // 65536 CTAs, one per bag
    grouped_embedding_bag_kernel<<<blocks, 128>>>(weights, values, offsets, out);
}

// round 5
// speedup vs baseline: 1.0384x; 1.0384x over previous
#include <cuda_runtime.h>
#include <cuda_bf16.h>

// GroupedEmbeddingBag: T tables [N, D] fp32; per table L indices pooled into B
// bags (sum, include_last_offset). Output [B, T*D].
//
// R5: CTA-per-bag (128 thr, 4 warps interleaved) + SMEM INDEX STAGING.
// A bag's indices are contiguous in values[], so the 128 threads stage the
// whole bag into smem with 1-2 coalesced loads; the gather mainloop then reads
// indices from smem (off the global-latency chain) and issues pure 512B row
// gathers. t-major grid order preserved (keeps active table L2-resident;
// measured traffic ~97% of compulsory — protect).

#define T_TABLES 8
#define N_ROWS   200000
#define D_DIM    128
#define B_BAGS   8192
#define L_IDX    163840
#define CHUNK    256     // staged indices per pass (covers max bag ~200)

__global__ __launch_bounds__(128, 16)
void grouped_embedding_bag_kernel(const float*  __restrict__ weights,
                                  const int*    __restrict__ values,
                                  const int*    __restrict__ offsets,
                                  float*        __restrict__ out)
{
    const int t = blockIdx.x >> 13;           // / B_BAGS  (t-major: keep!)
    const int b = blockIdx.x & (B_BAGS - 1);
    const int warp = threadIdx.x >> 5;        // 0..3
    const int lane = threadIdx.x & 31;

    const int* __restrict__ offs_t = offsets + t * (B_BAGS + 1) + b;
    const int start = __ldg(offs_t);
    const int end   = __ldg(offs_t + 1);

    const int* __restrict__ vals_t = values + (size_t)t * L_IDX;
    const float4* __restrict__ base =
        reinterpret_cast<const float4*>(weights + (size_t)t * N_ROWS * D_DIM) + lane;

    __shared__ int    s_idx[CHUNK + 16];      // +16 pad: unconditional reads safe
    __shared__ float4 red[4][32];

    float4 acc = make_float4(0.f, 0.f, 0.f, 0.f);

    for (int cbase = start; cbase < end; cbase += CHUNK) {
        const int n = min(end - cbase, CHUNK);

        // Stage this chunk's indices (coalesced; 1 transaction for avg bag).
        for (int k = threadIdx.x; k < n; k += 128)
            s_idx[k] = __ldg(vals_t + cbase + k);
        if (threadIdx.x < 16) s_idx[n + threadIdx.x] = 0;   // pad (row 0, harmless: gathers predicated)
        __syncthreads();

        // Warp `warp` takes positions warp, warp+4, ... ; unroll 4 (stride 16)
        // -> 4 independent 512B row gathers in flight, indices from smem.
        for (int p = warp; p < n; p += 16) {
            const int i0 = s_idx[p];
            const int i1 = s_idx[p + 4];      // padded-safe reads
            const int i2 = s_idx[p + 8];
            const int i3 = s_idx[p + 12];

            const float4 v0 = __ldg(base + (size_t)i0 * 32);
            acc.x += v0.x; acc.y += v0.y; acc.z += v0.z; acc.w += v0.w;
            if (p + 4 < n) {
                const float4 v = __ldg(base + (size_t)i1 * 32);
                acc.x += v.x; acc.y += v.y; acc.z += v.z; acc.w += v.w;
            }
            if (p + 8 < n) {
                const float4 v = __ldg(base + (size_t)i2 * 32);
                acc.x += v.x; acc.y += v.y; acc.z += v.z; acc.w += v.w;
            }
            if (p + 12 < n) {
                const float4 v = __ldg(base + (size_t)i3 * 32);
                acc.x += v.x; acc.y += v.y; acc.z += v.z; acc.w += v.w;
            }
        }
        __syncthreads();                      // protect restage (rare 2nd chunk)
    }

    // Reduce 4 warps' partials through smem.
    red[warp][lane] = acc;
    __syncthreads();

    if (warp == 0) {
        const float4 a1 = red[1][lane];
        const float4 a2 = red[2][lane];
        const float4 a3 = red[3][lane];
        acc.x += (a1.x + a2.x) + a3.x;
        acc.y += (a1.y + a2.y) + a3.y;
        acc.z += (a1.z + a2.z) + a3.z;
        acc.w += (a1.w + a2.w) + a3.w;
        float4* __restrict__ o =
            reinterpret_cast<float4*>(out + (size_t)b * (T_TABLES * D_DIM) + t * D_DIM) + lane;
        *o = acc;
    }
}

extern "C" void kernel_launch(void* const* d_in, const int* in_sizes, int n_in,
                              void* d_out, int out_size)
{
    const float* weights = (const float*)d_in[0];  // [T, N, D] f32
    const int*   values  = (const int*)  d_in[1];  // [T, L]    i32
    const int*   offsets = (const int*)  d_in[2];  // [T, B+1]  i32
    float*       out     = (float*)d_out;          // [B, T*D]  f32

    const int blocks = T_TABLES * B_BAGS;          // 65536 CTAs, one per bag
    grouped_embedding_bag_kernel<<<blocks, 128>>>(weights, values, offsets, out);
}

// round 6
// speedup vs baseline: 1.0802x; 1.0403x over previous
#include <cuda_runtime.h>
#include <cuda_bf16.h>

// GroupedEmbeddingBag: T tables [N, D] fp32; per table L indices pooled into B
// bags (sum, include_last_offset). Output [B, T*D].
//
// R6: 64-thread CTA per (t,b) bag, 2 warps position-interleaved. Rationale:
// at 128thr/CTA each warp owned only ~5 rows, so fixed per-CTA overhead
// (offsets -> stage -> syncs -> reduce) rivaled the gather phase and starved
// DRAM (stuck ~65%). 64thr doubles per-warp gather work at identical SM-wide
// thread count (32 CTA slots x 64 = 2048 thr/SM). Indices staged in smem,
// unroll-4 predicated gathers (4 independent 512B row loads in flight).
// t-major grid order preserved (active table stays L2-resident; traffic is
// ~97% of compulsory — protect).

#define T_TABLES 8
#define N_ROWS   200000
#define D_DIM    128
#define B_BAGS   8192
#define L_IDX    163840
#define CHUNK    256     // staged indices per pass (covers max bag ~200)

__global__ __launch_bounds__(64, 32)
void grouped_embedding_bag_kernel(const float*  __restrict__ weights,
                                  const int*    __restrict__ values,
                                  const int*    __restrict__ offsets,
                                  float*        __restrict__ out)
{
    const int t = blockIdx.x >> 13;           // / B_BAGS  (t-major: keep!)
    const int b = blockIdx.x & (B_BAGS - 1);
    const int warp = threadIdx.x >> 5;        // 0..1
    const int lane = threadIdx.x & 31;

    const int* __restrict__ offs_t = offsets + t * (B_BAGS + 1) + b;
    const int start = __ldg(offs_t);
    const int end   = __ldg(offs_t + 1);

    const int* __restrict__ vals_t = values + (size_t)t * L_IDX;
    const float4* __restrict__ base =
        reinterpret_cast<const float4*>(weights + (size_t)t * N_ROWS * D_DIM) + lane;

    __shared__ int    s_idx[CHUNK + 8];       // +8 pad: unconditional reads safe
    __shared__ float4 red[32];

    float4 acc = make_float4(0.f, 0.f, 0.f, 0.f);

    for (int cbase = start; cbase < end; cbase += CHUNK) {
        if (cbase != start) __syncthreads();  // protect restage (rare)
        const int n = min(end - cbase, CHUNK);

        // Stage this chunk's indices (coalesced).
        for (int k = threadIdx.x; k < n; k += 64)
            s_idx[k] = __ldg(vals_t + cbase + k);
        if (threadIdx.x < 8) s_idx[n + threadIdx.x] = 0;   // pad
        __syncthreads();

        // Warp w takes positions w, w+2, w+4, ...; unroll 4 (stride 8):
        // 4 independent 512B row gathers in flight, indices from smem.
        for (int p = warp; p < n; p += 8) {
            const int i0 = s_idx[p];
            const int i1 = s_idx[p + 2];      // padded-safe reads
            const int i2 = s_idx[p + 4];
            const int i3 = s_idx[p + 6];

            const float4 v0 = __ldg(base + (size_t)i0 * 32);
            acc.x += v0.x; acc.y += v0.y; acc.z += v0.z; acc.w += v0.w;
            if (p + 2 < n) {
                const float4 v = __ldg(base + (size_t)i1 * 32);
                acc.x += v.x; acc.y += v.y; acc.z += v.z; acc.w += v.w;
            }
            if (p + 4 < n) {
                const float4 v = __ldg(base + (size_t)i2 * 32);
                acc.x += v.x; acc.y += v.y; acc.z += v.z; acc.w += v.w;
            }
            if (p + 6 < n) {
                const float4 v = __ldg(base + (size_t)i3 * 32);
                acc.x += v.x; acc.y += v.y; acc.z += v.z; acc.w += v.w;
            }
        }
    }

    // Reduce the 2 warps' partials through smem.
    if (warp == 1) red[lane] = acc;
    __syncthreads();

    if (warp == 0) {
        const float4 a1 = red[lane];
        acc.x += a1.x; acc.y += a1.y; acc.z += a1.z; acc.w += a1.w;
        float4* __restrict__ o =
            reinterpret_cast<float4*>(out + (size_t)b * (T_TABLES * D_DIM) + t * D_DIM) + lane;
        *o = acc;
    }
}

extern "C" void kernel_launch(void* const* d_in, const int* in_sizes, int n_in,
                              void* d_out, int out_size)
{
    const float* weights = (const float*)d_in[0];  // [T, N, D] f32
    const int*   values  = (const int*)  d_in[1];  // [T, L]    i32
    const int*   offsets = (const int*)  d_in[2];  // [T, B+1]  i32
    float*       out     = (float*)d_out;          // [B, T*D]  f32

    const int blocks = T_TABLES * B_BAGS;          // 65536 CTAs, one per bag
    grouped_embedding_bag_kernel<<<blocks, 64>>>(weights, values, offsets, out);
}